// round 12
// baseline (speedup 1.0000x reference)
#include <cuda_runtime.h>

#define IN_C    128
#define OUT_C   64
#define EDGE_DIM 16
#define EDGE_HID 32
#define NMAX    100000
#define EMAX    1600000
#define NBLK    296
#define NTHR    512
#define SCANB   1024

typedef unsigned long long u64;

__device__ __forceinline__ u64 pk(float lo, float hi) {
    u64 r; asm("mov.b64 %0, {%1,%2};" : "=l"(r) : "f"(lo), "f"(hi)); return r;
}
__device__ __forceinline__ void upk(u64 v, float& lo, float& hi) {
    asm("mov.b64 {%0,%1}, %2;" : "=f"(lo), "=f"(hi) : "l"(v));
}
__device__ __forceinline__ void fma2(u64& d, u64 a, u64 b) {
    asm("fma.rn.f32x2 %0, %1, %2, %0;" : "+l"(d) : "l"(a), "l"(b));
}

// ---------------- scratch ------------------------------------------------------
// INVARIANT (holds at entry of every kernel_launch call; established by
// module-load zero-init on the first call, restored by k_norm on every call):
//   g_degacc == 0, g_cnt == 0, g_cur2 == 0, g_sum == 0, g_sumsq == 0,
//   g_ctr == 0, g_ctr2 == 0, g_ctrS == 0
static __device__ float g_ew[EMAX];
static __device__ float g_degacc[NMAX];   // weighted in-degree EXCLUDING self loop
static __device__ float g_xt[(long long)NMAX * OUT_C];
static __device__ float g_sum[OUT_C];
static __device__ float g_sumsq[OUT_C];
static __device__ int   g_ctr;
static __device__ int   g_ctr2;
static __device__ int   g_ctrS;
// CSR
static __device__ int   g_cnt[NMAX];
static __device__ int   g_base[NMAX];     // intra-block exclusive prefix (scan1)
static __device__ int   g_cur2[NMAX];     // per-node fill cursor (invariant 0)
static __device__ int   g_bsum[(NMAX + SCANB - 1) / SCANB];
static __device__ int   g_boff[(NMAX + SCANB - 1) / SCANB];
static __device__ int   g_src[EMAX];
static __device__ int   g_eid[EMAX];

// ---------------- CSR: histogram (needs g_cnt==0 invariant) --------------------
__global__ void k_hist(const int* __restrict__ ei, int e_, int n) {
    int i = blockIdx.x * blockDim.x + threadIdx.x;
    if (i >= e_) return;
    int c = ei[e_ + i];
    if ((unsigned)c < (unsigned)n) atomicAdd(&g_cnt[c], 1);
}

// ---------------- CSR: block scan + fused last-block scan of block sums --------
__global__ void k_scan1(int n, int nb) {
    __shared__ int s[SCANB];
    __shared__ bool isLast;
    int t = threadIdx.x;
    int i = blockIdx.x * SCANB + t;
    int v = (i < n) ? g_cnt[i] : 0;
    s[t] = v;
    __syncthreads();
#pragma unroll
    for (int off = 1; off < SCANB; off <<= 1) {
        int x = (t >= off) ? s[t - off] : 0;
        __syncthreads();
        s[t] += x;
        __syncthreads();
    }
    if (i < n) g_base[i] = s[t] - v;                 // exclusive within block
    if (t == SCANB - 1) {
        g_bsum[blockIdx.x] = s[t];
        __threadfence();
        int old = atomicAdd(&g_ctrS, 1);
        isLast = (old == nb - 1);
    }
    __syncthreads();
    if (isLast) {
        __threadfence();
        // scan nb (<=128) block sums with the first 128 threads
        __shared__ int bs[128];
        if (t < 128) bs[t] = (t < nb) ? g_bsum[t] : 0;
        __syncthreads();
        if (t < 128) {
#pragma unroll
            for (int off = 1; off < 128; off <<= 1) {
                int x = (t >= off) ? bs[t - off] : 0;
                __syncthreads();
                bs[t] += x;
                __syncthreads();
            }
        } else {
#pragma unroll
            for (int off = 1; off < 128; off <<= 1) { __syncthreads(); __syncthreads(); }
        }
        if (t < nb) g_boff[t] = bs[t] - g_bsum[t];   // exclusive
        if (t == 0) g_ctrS = 0;                      // restore invariant
    }
}

// ---------------- CSR: fill (needs g_cur2==0 invariant) ------------------------
__global__ void k_fill(const int* __restrict__ ei, int e_, int n) {
    int i = blockIdx.x * blockDim.x + threadIdx.x;
    if (i >= e_) return;
    int r = ei[i];
    int c = ei[e_ + i];
    if ((unsigned)r >= (unsigned)n || (unsigned)c >= (unsigned)n) return;
    int base = g_base[c] + g_boff[c >> 10];
    int slot = base + atomicAdd(&g_cur2[c], 1);
    g_src[slot] = r;
    g_eid[slot] = i;
}

// ---------------- edge MLP, f32x2 over h-pairs, 2 edges/thread -----------------
// needs g_degacc==0 invariant
__global__ void k_edge_mlp(const float* __restrict__ ea,
                           const float* __restrict__ w1, const float* __restrict__ b1,
                           const float* __restrict__ w2, const float* __restrict__ b2,
                           const int* __restrict__ ei, int e_, int n) {
    __shared__ __align__(16) float2 swp[16 * 16];
    __shared__ __align__(8)  float2 sb1p[16];
    __shared__ float sw2[EDGE_HID];
    __shared__ float sb2;
    {
        int t = threadIdx.x;
        if (t < 256) {
            int p = t >> 4, i = t & 15;
            swp[t] = make_float2(w1[(2 * p) * EDGE_DIM + i], w1[(2 * p + 1) * EDGE_DIM + i]);
        }
        if (t < 16) sb1p[t] = make_float2(b1[2 * t], b1[2 * t + 1]);
        if (t < EDGE_HID) sw2[t] = w2[t];
        if (t == 0) sb2 = b2[0];
    }
    __syncthreads();

    int e0 = (blockIdx.x * blockDim.x + threadIdx.x) * 2;
    if (e0 >= e_) return;
    bool two = (e0 + 1) < e_;

    u64 a0p[EDGE_DIM], a1p[EDGE_DIM];
    {
        const float4* p = (const float4*)(ea + (long long)e0 * EDGE_DIM);
#pragma unroll
        for (int q = 0; q < 4; q++) {
            float4 v = p[q];
            a0p[q*4+0] = pk(v.x, v.x); a0p[q*4+1] = pk(v.y, v.y);
            a0p[q*4+2] = pk(v.z, v.z); a0p[q*4+3] = pk(v.w, v.w);
            float4 u = two ? p[q + 4] : make_float4(0.f, 0.f, 0.f, 0.f);
            a1p[q*4+0] = pk(u.x, u.x); a1p[q*4+1] = pk(u.y, u.y);
            a1p[q*4+2] = pk(u.z, u.z); a1p[q*4+3] = pk(u.w, u.w);
        }
    }

    float acc0 = sb2, acc1 = sb2;
#pragma unroll 4
    for (int p = 0; p < 16; ++p) {
        float2 sb = sb1p[p];
        u64 s0 = pk(sb.x, sb.y);
        u64 s1 = s0;
#pragma unroll
        for (int iq = 0; iq < 8; ++iq) {
            ulonglong2 w = *(const ulonglong2*)&swp[p * 16 + iq * 2];
            fma2(s0, a0p[iq*2],   w.x);
            fma2(s0, a0p[iq*2+1], w.y);
            fma2(s1, a1p[iq*2],   w.x);
            fma2(s1, a1p[iq*2+1], w.y);
        }
        float wlo = sw2[2*p], whi = sw2[2*p+1];
        float t0, t1;
        upk(s0, t0, t1);
        acc0 = fmaf(fmaxf(t0, 0.f), wlo, fmaf(fmaxf(t1, 0.f), whi, acc0));
        upk(s1, t0, t1);
        acc1 = fmaf(fmaxf(t0, 0.f), wlo, fmaf(fmaxf(t1, 0.f), whi, acc1));
    }
    float g0 = 1.0f / (1.0f + __expf(-acc0));
    g_ew[e0] = g0;
    int c0 = ei[e_ + e0];
    if ((unsigned)c0 < (unsigned)n) atomicAdd(&g_degacc[c0], g0);
    if (two) {
        float g1 = 1.0f / (1.0f + __expf(-acc1));
        g_ew[e0 + 1] = g1;
        int c1 = ei[e_ + e0 + 1];
        if ((unsigned)c1 < (unsigned)n) atomicAdd(&g_degacc[c1], g1);
    }
}

// ---------------- xt = x @ lin_w.T (pure GEMM, fp32/f32x2) ----------------------
#define GR 128
#define KC 32
#define XROW 132
__global__ void __launch_bounds__(256, 3)
k_xt(const float* __restrict__ x, const float* __restrict__ lw, int n) {
    __shared__ __align__(16) float xs[KC][XROW];
    __shared__ __align__(16) float ws[KC][OUT_C];
    int r0 = blockIdx.x * GR;
    int tx = threadIdx.x & 15;
    int ty = threadIdx.x >> 4;
    u64 accp[4][4] = {};

    for (int k0 = 0; k0 < IN_C; k0 += KC) {
        for (int i = threadIdx.x; i < GR * (KC / 4); i += 256) {
            int r = i >> 3, kq = i & 7;
            float4 v = make_float4(0.f, 0.f, 0.f, 0.f);
            if (r0 + r < n) v = *(const float4*)(x + (long long)(r0 + r) * IN_C + k0 + kq * 4);
            xs[kq*4+0][r] = v.x; xs[kq*4+1][r] = v.y;
            xs[kq*4+2][r] = v.z; xs[kq*4+3][r] = v.w;
        }
        for (int i = threadIdx.x; i < OUT_C * (KC / 4); i += 256) {
            int o = i >> 3, kq = i & 7;
            float4 v = *(const float4*)(lw + (long long)o * IN_C + k0 + kq * 4);
            ws[kq*4+0][o] = v.x; ws[kq*4+1][o] = v.y;
            ws[kq*4+2][o] = v.z; ws[kq*4+3][o] = v.w;
        }
        __syncthreads();
#pragma unroll 8
        for (int k = 0; k < KC; ++k) {
            float4 a0 = *(const float4*)&xs[k][ty * 8];
            float4 a1 = *(const float4*)&xs[k][ty * 8 + 4];
            float4 b  = *(const float4*)&ws[k][tx * 4];
            u64 ap0 = pk(a0.x, a0.y), ap1 = pk(a0.z, a0.w);
            u64 ap2 = pk(a1.x, a1.y), ap3 = pk(a1.z, a1.w);
            u64 b0 = pk(b.x, b.x), b1 = pk(b.y, b.y), b2 = pk(b.z, b.z), b3 = pk(b.w, b.w);
            fma2(accp[0][0], ap0, b0); fma2(accp[0][1], ap0, b1);
            fma2(accp[0][2], ap0, b2); fma2(accp[0][3], ap0, b3);
            fma2(accp[1][0], ap1, b0); fma2(accp[1][1], ap1, b1);
            fma2(accp[1][2], ap1, b2); fma2(accp[1][3], ap1, b3);
            fma2(accp[2][0], ap2, b0); fma2(accp[2][1], ap2, b1);
            fma2(accp[2][2], ap2, b2); fma2(accp[2][3], ap2, b3);
            fma2(accp[3][0], ap3, b0); fma2(accp[3][1], ap3, b1);
            fma2(accp[3][2], ap3, b2); fma2(accp[3][3], ap3, b3);
        }
        __syncthreads();
    }
#pragma unroll
    for (int rp = 0; rp < 4; ++rp) {
        float lo[4], hi[4];
#pragma unroll
        for (int j = 0; j < 4; ++j) upk(accp[rp][j], lo[j], hi[j]);
        int rA = r0 + ty * 8 + rp * 2;
        int rB = rA + 1;
        if (rA < n)
            *(float4*)&g_xt[(long long)rA * OUT_C + tx * 4] = make_float4(lo[0], lo[1], lo[2], lo[3]);
        if (rB < n)
            *(float4*)&g_xt[(long long)rB * OUT_C + tx * 4] = make_float4(hi[0], hi[1], hi[2], hi[3]);
    }
}

// ---------------- gather + self-loop + bias + PReLU (1 warp/node) --------------
__global__ void __launch_bounds__(256)
k_gather(float* __restrict__ out, const float* __restrict__ bias,
         const float* __restrict__ pa, int n) {
    int node = blockIdx.x * 8 + (threadIdx.x >> 5);
    if (node >= n) return;
    int lane = threadIdx.x & 31;
    int c0 = lane * 2;
    int beg = g_base[node] + g_boff[node >> 10];
    int cnt = g_cnt[node];
    float2 acc = make_float2(0.f, 0.f);

    for (int j0 = 0; j0 < cnt; j0 += 32) {
        int m = min(32, cnt - j0);
        int src = 0; float a = 0.f;
        if (lane < m) {
            int slot = beg + j0 + lane;
            src = g_src[slot];
            a = rsqrtf(1.0f + g_degacc[src]) * g_ew[g_eid[slot]];
        }
#pragma unroll 4
        for (int j = 0; j < m; ++j) {
            int   s  = __shfl_sync(0xffffffffu, src, j);
            float aj = __shfl_sync(0xffffffffu, a, j);
            float2 v = *(const float2*)&g_xt[(long long)s * OUT_C + c0];
            acc.x = fmaf(aj, v.x, acc.x);
            acc.y = fmaf(aj, v.y, acc.y);
        }
    }
    float dc = rsqrtf(1.0f + g_degacc[node]);
    float d2 = dc * dc;
    float2 xv = *(const float2*)&g_xt[(long long)node * OUT_C + c0];
    float pr = pa[0];
    float v0 = fmaf(d2, xv.x, acc.x * dc) + bias[c0];
    float v1 = fmaf(d2, xv.y, acc.y * dc) + bias[c0 + 1];
    v0 = (v0 >= 0.f) ? v0 : pr * v0;
    v1 = (v1 >= 0.f) ? v1 : pr * v1;
    *(float2*)&out[(long long)node * OUT_C + c0] = make_float2(v0, v1);
}

// ---------------- GraphNorm (resident) + invariant restoration -----------------
__global__ void __launch_bounds__(NTHR, 2)
k_norm(float* __restrict__ y,
       const float* __restrict__ gw, const float* __restrict__ gb,
       const float* __restrict__ gms, int n, int rowsPerBlk) {
    extern __shared__ float sm[];
    __shared__ float ss[NTHR], sq[NTHR];
    __shared__ bool lastBlk;

    int tid = threadIdx.x;
    int c = tid & 63;
    int rl = tid >> 6;
    int r0 = blockIdx.x * rowsPerBlk;
    int r1 = min(n, r0 + rowsPerBlk);

    // phase 0a: restore invariants for arrays dead after k_gather (hidden, parallel)
    for (int i = r0 + tid; i < r1; i += NTHR) {
        g_degacc[i] = 0.0f;
        g_cnt[i] = 0;
        g_cur2[i] = 0;
    }

    // phase 0b: load + stats
    float s = 0.0f, q = 0.0f;
    for (int r = r0 + rl; r < r1; r += NTHR / 64) {
        float v = y[(long long)r * OUT_C + c];
        sm[(r - r0) * OUT_C + c] = v;
        s += v;
        q = fmaf(v, v, q);
    }
    ss[tid] = s; sq[tid] = q;
    __syncthreads();
    if (tid < 64) {
        s = 0.f; q = 0.f;
#pragma unroll
        for (int i = 0; i < NTHR; i += 64) { s += ss[tid + i]; q += sq[tid + i]; }
        atomicAdd(&g_sum[tid], s);
        atomicAdd(&g_sumsq[tid], q);
    }
    __syncthreads();

    // device-wide barrier
    if (tid == 0) {
        __threadfence();
        atomicAdd(&g_ctr, 1);
        while (*((volatile int*)&g_ctr) < gridDim.x) __nanosleep(40);
    }
    __syncthreads();
    __threadfence();

    float invn = 1.0f / (float)n;
    float m  = (*((volatile float*)&g_sum[c]))   * invn;
    float qq = (*((volatile float*)&g_sumsq[c])) * invn;
    float sc = gms[c];
    float var = fmaf(-2.0f * sc * m, m, qq) + sc * sc * m * m;
    float w = gw[c] * rsqrtf(var + 1e-5f);
    float smean = sc * m;
    float bb = gb[c];

    for (int r = r0 + rl; r < r1; r += NTHR / 64) {
        long long idx = (long long)r * OUT_C + c;
        y[idx] = fmaf(sm[(r - r0) * OUT_C + c] - smean, w, bb);
    }

    // phase 2: designated last block restores stats/barrier invariants.
    // All blocks have READ g_sum/g_sumsq (into registers) before arriving here.
    __syncthreads();
    if (tid == 0) {
        __threadfence();
        int old = atomicAdd(&g_ctr2, 1);
        lastBlk = (old == (int)gridDim.x - 1);
    }
    __syncthreads();
    if (lastBlk && tid < 64) {
        g_sum[tid] = 0.0f;
        g_sumsq[tid] = 0.0f;
        if (tid == 0) { g_ctr = 0; g_ctr2 = 0; }
    }
}

// ---------------- launch ---------------------------------------------------------
extern "C" void kernel_launch(void* const* d_in, const int* in_sizes, int n_in,
                              void* d_out, int out_size) {
    const float* x    = (const float*)d_in[0];
    const int*   ei   = (const int*)d_in[1];
    const float* ea   = (const float*)d_in[2];
    const float* lw   = (const float*)d_in[3];
    const float* bias = (const float*)d_in[4];
    const float* w1   = (const float*)d_in[5];
    const float* b1   = (const float*)d_in[6];
    const float* w2   = (const float*)d_in[7];
    const float* b2   = (const float*)d_in[8];
    const float* pa   = (const float*)d_in[9];
    const float* gw   = (const float*)d_in[10];
    const float* gb   = (const float*)d_in[11];
    const float* gms  = (const float*)d_in[12];
    float* out = (float*)d_out;

    int n = in_sizes[0] / IN_C;
    int e = in_sizes[1] / 2;
    int rowsPerBlk = (n + NBLK - 1) / NBLK;
    size_t smBytes = (size_t)rowsPerBlk * OUT_C * sizeof(float);
    int nb = (n + SCANB - 1) / SCANB;

    static cudaStream_t s1 = nullptr, s2 = nullptr;
    static cudaEvent_t evFork = nullptr, evJ1 = nullptr, evJ2 = nullptr;
    if (s1 == nullptr) {
        cudaStreamCreateWithFlags(&s1, cudaStreamNonBlocking);
        cudaStreamCreateWithFlags(&s2, cudaStreamNonBlocking);
        cudaEventCreateWithFlags(&evFork, cudaEventDisableTiming);
        cudaEventCreateWithFlags(&evJ1, cudaEventDisableTiming);
        cudaEventCreateWithFlags(&evJ2, cudaEventDisableTiming);
        cudaFuncSetAttribute(k_norm, cudaFuncAttributeMaxDynamicSharedMemorySize, 96 * 1024);
    }

    cudaEventRecord(evFork, 0);
    cudaStreamWaitEvent(s1, evFork, 0);
    cudaStreamWaitEvent(s2, evFork, 0);

    // stream1: GEMM
    k_xt<<<(n + GR - 1) / GR, 256, 0, s1>>>(x, lw, n);
    cudaEventRecord(evJ1, s1);

    // stream2: CSR build (3 kernels)
    k_hist<<<(e + 255) / 256, 256, 0, s2>>>(ei, e, n);
    k_scan1<<<nb, SCANB, 0, s2>>>(n, nb);
    k_fill<<<(e + 255) / 256, 256, 0, s2>>>(ei, e, n);
    cudaEventRecord(evJ2, s2);

    // main stream: edge gate MLP (starts immediately — no init kernel)
    int th_mlp = (e + 1) / 2;
    k_edge_mlp<<<(th_mlp + 255) / 256, 256>>>(ea, w1, b1, w2, b2, ei, e, n);

    cudaStreamWaitEvent(0, evJ1, 0);
    cudaStreamWaitEvent(0, evJ2, 0);

    k_gather<<<(n + 7) / 8, 256>>>(out, bias, pa, n);
    k_norm<<<NBLK, NTHR, smBytes>>>(out, gw, gb, gms, n, rowsPerBlk);
}

// round 13
// speedup vs baseline: 1.0492x; 1.0492x over previous
#include <cuda_runtime.h>

#define IN_C    128
#define OUT_C   64
#define EDGE_DIM 16
#define EDGE_HID 32
#define NMAX    100000
#define EMAX    1600000
#define NBLK    296
#define NTHR    512
#define SCANB   1024

typedef unsigned long long u64;

__device__ __forceinline__ u64 pk(float lo, float hi) {
    u64 r; asm("mov.b64 %0, {%1,%2};" : "=l"(r) : "f"(lo), "f"(hi)); return r;
}
__device__ __forceinline__ void upk(u64 v, float& lo, float& hi) {
    asm("mov.b64 {%0,%1}, %2;" : "=f"(lo), "=f"(hi) : "l"(v));
}
__device__ __forceinline__ void fma2(u64& d, u64 a, u64 b) {
    asm("fma.rn.f32x2 %0, %1, %2, %0;" : "+l"(d) : "l"(a), "l"(b));
}

// ---------------- scratch ------------------------------------------------------
// INVARIANT at entry of every kernel_launch (module-load zeros on first call;
// restored by k_norm / k_scan1 every call):
//   g_degacc==0, g_cnt==0, g_cur2==0, g_sum==0, g_sumsq==0,
//   g_ctr==0, g_ctr2==0, g_ctrS==0
static __device__ float g_ew[EMAX];
static __device__ float g_degacc[NMAX];   // weighted in-degree EXCLUDING self loop
static __device__ float g_xt[(long long)NMAX * OUT_C];
static __device__ float g_sum[OUT_C];
static __device__ float g_sumsq[OUT_C];
static __device__ int   g_ctr;
static __device__ int   g_ctr2;
static __device__ int   g_ctrS;
// CSR
static __device__ int   g_cnt[NMAX];
static __device__ int   g_base[NMAX];     // intra-block exclusive prefix (scan1)
static __device__ int   g_cur2[NMAX];     // per-node fill cursor (invariant 0)
static __device__ int   g_bsum[(NMAX + SCANB - 1) / SCANB];
static __device__ int   g_boff[(NMAX + SCANB - 1) / SCANB];
static __device__ u64   g_pack[EMAX];     // (eid << 32) | src  — single 8B payload

// ---------------- CSR: histogram (2 edges/thread) ------------------------------
__global__ void k_hist(const int* __restrict__ ei, int e_, int n) {
    int i0 = (blockIdx.x * blockDim.x + threadIdx.x) * 2;
    if (i0 >= e_) return;
    int c0 = ei[e_ + i0];
    if ((unsigned)c0 < (unsigned)n) atomicAdd(&g_cnt[c0], 1);
    if (i0 + 1 < e_) {
        int c1 = ei[e_ + i0 + 1];
        if ((unsigned)c1 < (unsigned)n) atomicAdd(&g_cnt[c1], 1);
    }
}

// ---------------- CSR: block scan + fused last-block scan of block sums --------
__global__ void k_scan1(int n, int nb) {
    __shared__ int s[SCANB];
    __shared__ bool isLast;
    int t = threadIdx.x;
    int i = blockIdx.x * SCANB + t;
    int v = (i < n) ? g_cnt[i] : 0;
    s[t] = v;
    __syncthreads();
#pragma unroll
    for (int off = 1; off < SCANB; off <<= 1) {
        int x = (t >= off) ? s[t - off] : 0;
        __syncthreads();
        s[t] += x;
        __syncthreads();
    }
    if (i < n) g_base[i] = s[t] - v;                 // exclusive within block
    if (t == SCANB - 1) {
        g_bsum[blockIdx.x] = s[t];
        __threadfence();
        int old = atomicAdd(&g_ctrS, 1);
        isLast = (old == nb - 1);
    }
    __syncthreads();
    if (isLast) {
        __threadfence();
        __shared__ int bs[128];
        if (t < 128) bs[t] = (t < nb) ? g_bsum[t] : 0;
        __syncthreads();
        if (t < 128) {
#pragma unroll
            for (int off = 1; off < 128; off <<= 1) {
                int x = (t >= off) ? bs[t - off] : 0;
                __syncthreads();
                bs[t] += x;
                __syncthreads();
            }
        } else {
#pragma unroll
            for (int off = 1; off < 128; off <<= 1) { __syncthreads(); __syncthreads(); }
        }
        if (t < nb) g_boff[t] = bs[t] - g_bsum[t];   // exclusive
        if (t == 0) g_ctrS = 0;                      // restore invariant
    }
}

// ---------------- CSR: fill (packed u64 payload, one scattered STG.64) ---------
__global__ void k_fill(const int* __restrict__ ei, int e_, int n) {
    int i = blockIdx.x * blockDim.x + threadIdx.x;
    if (i >= e_) return;
    int r = ei[i];
    int c = ei[e_ + i];
    if ((unsigned)r >= (unsigned)n || (unsigned)c >= (unsigned)n) return;
    int base = g_base[c] + g_boff[c >> 10];
    int slot = base + atomicAdd(&g_cur2[c], 1);
    g_pack[slot] = ((u64)(unsigned)i << 32) | (unsigned)r;
}

// ---------------- edge MLP, f32x2 over h-pairs, 2 edges/thread -----------------
__global__ void k_edge_mlp(const float* __restrict__ ea,
                           const float* __restrict__ w1, const float* __restrict__ b1,
                           const float* __restrict__ w2, const float* __restrict__ b2,
                           const int* __restrict__ ei, int e_, int n) {
    __shared__ __align__(16) float2 swp[16 * 16];
    __shared__ __align__(8)  float2 sb1p[16];
    __shared__ float sw2[EDGE_HID];
    __shared__ float sb2;
    {
        int t = threadIdx.x;
        if (t < 256) {
            int p = t >> 4, i = t & 15;
            swp[t] = make_float2(w1[(2 * p) * EDGE_DIM + i], w1[(2 * p + 1) * EDGE_DIM + i]);
        }
        if (t < 16) sb1p[t] = make_float2(b1[2 * t], b1[2 * t + 1]);
        if (t < EDGE_HID) sw2[t] = w2[t];
        if (t == 0) sb2 = b2[0];
    }
    __syncthreads();

    int e0 = (blockIdx.x * blockDim.x + threadIdx.x) * 2;
    if (e0 >= e_) return;
    bool two = (e0 + 1) < e_;

    u64 a0p[EDGE_DIM], a1p[EDGE_DIM];
    {
        const float4* p = (const float4*)(ea + (long long)e0 * EDGE_DIM);
#pragma unroll
        for (int q = 0; q < 4; q++) {
            float4 v = p[q];
            a0p[q*4+0] = pk(v.x, v.x); a0p[q*4+1] = pk(v.y, v.y);
            a0p[q*4+2] = pk(v.z, v.z); a0p[q*4+3] = pk(v.w, v.w);
            float4 u = two ? p[q + 4] : make_float4(0.f, 0.f, 0.f, 0.f);
            a1p[q*4+0] = pk(u.x, u.x); a1p[q*4+1] = pk(u.y, u.y);
            a1p[q*4+2] = pk(u.z, u.z); a1p[q*4+3] = pk(u.w, u.w);
        }
    }

    float acc0 = sb2, acc1 = sb2;
#pragma unroll 4
    for (int p = 0; p < 16; ++p) {
        float2 sb = sb1p[p];
        u64 s0 = pk(sb.x, sb.y);
        u64 s1 = s0;
#pragma unroll
        for (int iq = 0; iq < 8; ++iq) {
            ulonglong2 w = *(const ulonglong2*)&swp[p * 16 + iq * 2];
            fma2(s0, a0p[iq*2],   w.x);
            fma2(s0, a0p[iq*2+1], w.y);
            fma2(s1, a1p[iq*2],   w.x);
            fma2(s1, a1p[iq*2+1], w.y);
        }
        float wlo = sw2[2*p], whi = sw2[2*p+1];
        float t0, t1;
        upk(s0, t0, t1);
        acc0 = fmaf(fmaxf(t0, 0.f), wlo, fmaf(fmaxf(t1, 0.f), whi, acc0));
        upk(s1, t0, t1);
        acc1 = fmaf(fmaxf(t0, 0.f), wlo, fmaf(fmaxf(t1, 0.f), whi, acc1));
    }
    float g0 = 1.0f / (1.0f + __expf(-acc0));
    g_ew[e0] = g0;
    int c0 = ei[e_ + e0];
    if ((unsigned)c0 < (unsigned)n) atomicAdd(&g_degacc[c0], g0);
    if (two) {
        float g1 = 1.0f / (1.0f + __expf(-acc1));
        g_ew[e0 + 1] = g1;
        int c1 = ei[e_ + e0 + 1];
        if ((unsigned)c1 < (unsigned)n) atomicAdd(&g_degacc[c1], g1);
    }
}

// ---------------- xt = x @ lin_w.T (pure GEMM, fp32/f32x2) ----------------------
#define GR 128
#define KC 32
#define XROW 132
__global__ void __launch_bounds__(256, 3)
k_xt(const float* __restrict__ x, const float* __restrict__ lw, int n) {
    __shared__ __align__(16) float xs[KC][XROW];
    __shared__ __align__(16) float ws[KC][OUT_C];
    int r0 = blockIdx.x * GR;
    int tx = threadIdx.x & 15;
    int ty = threadIdx.x >> 4;
    u64 accp[4][4] = {};

    for (int k0 = 0; k0 < IN_C; k0 += KC) {
        for (int i = threadIdx.x; i < GR * (KC / 4); i += 256) {
            int r = i >> 3, kq = i & 7;
            float4 v = make_float4(0.f, 0.f, 0.f, 0.f);
            if (r0 + r < n) v = *(const float4*)(x + (long long)(r0 + r) * IN_C + k0 + kq * 4);
            xs[kq*4+0][r] = v.x; xs[kq*4+1][r] = v.y;
            xs[kq*4+2][r] = v.z; xs[kq*4+3][r] = v.w;
        }
        for (int i = threadIdx.x; i < OUT_C * (KC / 4); i += 256) {
            int o = i >> 3, kq = i & 7;
            float4 v = *(const float4*)(lw + (long long)o * IN_C + k0 + kq * 4);
            ws[kq*4+0][o] = v.x; ws[kq*4+1][o] = v.y;
            ws[kq*4+2][o] = v.z; ws[kq*4+3][o] = v.w;
        }
        __syncthreads();
#pragma unroll 8
        for (int k = 0; k < KC; ++k) {
            float4 a0 = *(const float4*)&xs[k][ty * 8];
            float4 a1 = *(const float4*)&xs[k][ty * 8 + 4];
            float4 b  = *(const float4*)&ws[k][tx * 4];
            u64 ap0 = pk(a0.x, a0.y), ap1 = pk(a0.z, a0.w);
            u64 ap2 = pk(a1.x, a1.y), ap3 = pk(a1.z, a1.w);
            u64 b0 = pk(b.x, b.x), b1 = pk(b.y, b.y), b2 = pk(b.z, b.z), b3 = pk(b.w, b.w);
            fma2(accp[0][0], ap0, b0); fma2(accp[0][1], ap0, b1);
            fma2(accp[0][2], ap0, b2); fma2(accp[0][3], ap0, b3);
            fma2(accp[1][0], ap1, b0); fma2(accp[1][1], ap1, b1);
            fma2(accp[1][2], ap1, b2); fma2(accp[1][3], ap1, b3);
            fma2(accp[2][0], ap2, b0); fma2(accp[2][1], ap2, b1);
            fma2(accp[2][2], ap2, b2); fma2(accp[2][3], ap2, b3);
            fma2(accp[3][0], ap3, b0); fma2(accp[3][1], ap3, b1);
            fma2(accp[3][2], ap3, b2); fma2(accp[3][3], ap3, b3);
        }
        __syncthreads();
    }
#pragma unroll
    for (int rp = 0; rp < 4; ++rp) {
        float lo[4], hi[4];
#pragma unroll
        for (int j = 0; j < 4; ++j) upk(accp[rp][j], lo[j], hi[j]);
        int rA = r0 + ty * 8 + rp * 2;
        int rB = rA + 1;
        if (rA < n)
            *(float4*)&g_xt[(long long)rA * OUT_C + tx * 4] = make_float4(lo[0], lo[1], lo[2], lo[3]);
        if (rB < n)
            *(float4*)&g_xt[(long long)rB * OUT_C + tx * 4] = make_float4(hi[0], hi[1], hi[2], hi[3]);
    }
}

// ---------------- gather + self-loop + bias + PReLU (1 warp/node) --------------
__global__ void __launch_bounds__(256)
k_gather(float* __restrict__ out, const float* __restrict__ bias,
         const float* __restrict__ pa, int n) {
    int node = blockIdx.x * 8 + (threadIdx.x >> 5);
    if (node >= n) return;
    int lane = threadIdx.x & 31;
    int c0 = lane * 2;
    int beg = g_base[node] + g_boff[node >> 10];
    int cnt = g_cnt[node];
    float2 acc = make_float2(0.f, 0.f);

    for (int j0 = 0; j0 < cnt; j0 += 32) {
        int m = min(32, cnt - j0);
        int src = 0; float a = 0.f;
        if (lane < m) {
            u64 pkd = g_pack[beg + j0 + lane];
            src = (int)(unsigned)(pkd & 0xffffffffu);
            int eid = (int)(unsigned)(pkd >> 32);
            a = rsqrtf(1.0f + g_degacc[src]) * g_ew[eid];
        }
#pragma unroll 4
        for (int j = 0; j < m; ++j) {
            int   s  = __shfl_sync(0xffffffffu, src, j);
            float aj = __shfl_sync(0xffffffffu, a, j);
            float2 v = *(const float2*)&g_xt[(long long)s * OUT_C + c0];
            acc.x = fmaf(aj, v.x, acc.x);
            acc.y = fmaf(aj, v.y, acc.y);
        }
    }
    float dc = rsqrtf(1.0f + g_degacc[node]);
    float d2 = dc * dc;
    float2 xv = *(const float2*)&g_xt[(long long)node * OUT_C + c0];
    float pr = pa[0];
    float v0 = fmaf(d2, xv.x, acc.x * dc) + bias[c0];
    float v1 = fmaf(d2, xv.y, acc.y * dc) + bias[c0 + 1];
    v0 = (v0 >= 0.f) ? v0 : pr * v0;
    v1 = (v1 >= 0.f) ? v1 : pr * v1;
    *(float2*)&out[(long long)node * OUT_C + c0] = make_float2(v0, v1);
}

// ---------------- GraphNorm (resident) + invariant restoration -----------------
__global__ void __launch_bounds__(NTHR, 2)
k_norm(float* __restrict__ y,
       const float* __restrict__ gw, const float* __restrict__ gb,
       const float* __restrict__ gms, int n, int rowsPerBlk) {
    extern __shared__ float sm[];
    __shared__ float ss[NTHR], sq[NTHR];
    __shared__ bool lastBlk;

    int tid = threadIdx.x;
    int c = tid & 63;
    int rl = tid >> 6;
    int r0 = blockIdx.x * rowsPerBlk;
    int r1 = min(n, r0 + rowsPerBlk);

    // restore invariants for arrays dead after k_gather (parallel, hidden)
    for (int i = r0 + tid; i < r1; i += NTHR) {
        g_degacc[i] = 0.0f;
        g_cnt[i] = 0;
        g_cur2[i] = 0;
    }

    float s = 0.0f, q = 0.0f;
    for (int r = r0 + rl; r < r1; r += NTHR / 64) {
        float v = y[(long long)r * OUT_C + c];
        sm[(r - r0) * OUT_C + c] = v;
        s += v;
        q = fmaf(v, v, q);
    }
    ss[tid] = s; sq[tid] = q;
    __syncthreads();
    if (tid < 64) {
        s = 0.f; q = 0.f;
#pragma unroll
        for (int i = 0; i < NTHR; i += 64) { s += ss[tid + i]; q += sq[tid + i]; }
        atomicAdd(&g_sum[tid], s);
        atomicAdd(&g_sumsq[tid], q);
    }
    __syncthreads();

    if (tid == 0) {
        __threadfence();
        atomicAdd(&g_ctr, 1);
        while (*((volatile int*)&g_ctr) < gridDim.x) __nanosleep(40);
    }
    __syncthreads();
    __threadfence();

    float invn = 1.0f / (float)n;
    float m  = (*((volatile float*)&g_sum[c]))   * invn;
    float qq = (*((volatile float*)&g_sumsq[c])) * invn;
    float sc = gms[c];
    float var = fmaf(-2.0f * sc * m, m, qq) + sc * sc * m * m;
    float w = gw[c] * rsqrtf(var + 1e-5f);
    float smean = sc * m;
    float bb = gb[c];

    for (int r = r0 + rl; r < r1; r += NTHR / 64) {
        long long idx = (long long)r * OUT_C + c;
        y[idx] = fmaf(sm[(r - r0) * OUT_C + c] - smean, w, bb);
    }

    __syncthreads();
    if (tid == 0) {
        __threadfence();
        int old = atomicAdd(&g_ctr2, 1);
        lastBlk = (old == (int)gridDim.x - 1);
    }
    __syncthreads();
    if (lastBlk && tid < 64) {
        g_sum[tid] = 0.0f;
        g_sumsq[tid] = 0.0f;
        if (tid == 0) { g_ctr = 0; g_ctr2 = 0; }
    }
}

// ---------------- launch ---------------------------------------------------------
extern "C" void kernel_launch(void* const* d_in, const int* in_sizes, int n_in,
                              void* d_out, int out_size) {
    const float* x    = (const float*)d_in[0];
    const int*   ei   = (const int*)d_in[1];
    const float* ea   = (const float*)d_in[2];
    const float* lw   = (const float*)d_in[3];
    const float* bias = (const float*)d_in[4];
    const float* w1   = (const float*)d_in[5];
    const float* b1   = (const float*)d_in[6];
    const float* w2   = (const float*)d_in[7];
    const float* b2   = (const float*)d_in[8];
    const float* pa   = (const float*)d_in[9];
    const float* gw   = (const float*)d_in[10];
    const float* gb   = (const float*)d_in[11];
    const float* gms  = (const float*)d_in[12];
    float* out = (float*)d_out;

    int n = in_sizes[0] / IN_C;
    int e = in_sizes[1] / 2;
    int rowsPerBlk = (n + NBLK - 1) / NBLK;
    size_t smBytes = (size_t)rowsPerBlk * OUT_C * sizeof(float);
    int nb = (n + SCANB - 1) / SCANB;

    static cudaStream_t s1 = nullptr, s2 = nullptr;
    static cudaEvent_t evFork = nullptr, evJ1 = nullptr, evJ2 = nullptr;
    if (s1 == nullptr) {
        cudaStreamCreateWithFlags(&s1, cudaStreamNonBlocking);
        cudaStreamCreateWithFlags(&s2, cudaStreamNonBlocking);
        cudaEventCreateWithFlags(&evFork, cudaEventDisableTiming);
        cudaEventCreateWithFlags(&evJ1, cudaEventDisableTiming);
        cudaEventCreateWithFlags(&evJ2, cudaEventDisableTiming);
        cudaFuncSetAttribute(k_norm, cudaFuncAttributeMaxDynamicSharedMemorySize, 96 * 1024);
    }

    cudaEventRecord(evFork, 0);
    cudaStreamWaitEvent(s1, evFork, 0);
    cudaStreamWaitEvent(s2, evFork, 0);

    // stream1: GEMM
    k_xt<<<(n + GR - 1) / GR, 256, 0, s1>>>(x, lw, n);
    cudaEventRecord(evJ1, s1);

    // stream2: CSR build
    int th_h = (e + 1) / 2;
    k_hist<<<(th_h + 255) / 256, 256, 0, s2>>>(ei, e, n);
    k_scan1<<<nb, SCANB, 0, s2>>>(n, nb);
    k_fill<<<(e + 255) / 256, 256, 0, s2>>>(ei, e, n);
    cudaEventRecord(evJ2, s2);

    // main stream: edge gate MLP
    int th_mlp = (e + 1) / 2;
    k_edge_mlp<<<(th_mlp + 255) / 256, 256>>>(ea, w1, b1, w2, b2, ei, e, n);

    cudaStreamWaitEvent(0, evJ1, 0);
    cudaStreamWaitEvent(0, evJ2, 0);

    k_gather<<<(n + 7) / 8, 256>>>(out, bias, pa, n);
    k_norm<<<NBLK, NTHR, smBytes>>>(out, gw, gb, gms, n, rowsPerBlk);
}

// round 14
// speedup vs baseline: 1.0600x; 1.0103x over previous
#include <cuda_runtime.h>

#define IN_C    128
#define OUT_C   64
#define EDGE_DIM 16
#define EDGE_HID 32
#define NMAX    100000
#define EMAX    1600000
#define NBLK    296
#define NTHR    512
#define SCANB   1024

typedef unsigned long long u64;

__device__ __forceinline__ u64 pk(float lo, float hi) {
    u64 r; asm("mov.b64 %0, {%1,%2};" : "=l"(r) : "f"(lo), "f"(hi)); return r;
}
__device__ __forceinline__ void upk(u64 v, float& lo, float& hi) {
    asm("mov.b64 {%0,%1}, %2;" : "=f"(lo), "=f"(hi) : "l"(v));
}
__device__ __forceinline__ void fma2(u64& d, u64 a, u64 b) {
    asm("fma.rn.f32x2 %0, %1, %2, %0;" : "+l"(d) : "l"(a), "l"(b));
}

// ---------------- scratch ------------------------------------------------------
// INVARIANT at entry of every kernel_launch (module-load zeros on first call;
// restored by k_norm / k_scan1 every call):
//   g_degacc==0, g_cnt==0, g_sum==0, g_sumsq==0, g_ctr==0, g_ctr2==0, g_ctrS==0
static __device__ float g_ew[EMAX];
static __device__ float g_degacc[NMAX];   // weighted in-degree EXCLUDING self loop
static __device__ float g_xt[(long long)NMAX * OUT_C];
static __device__ float g_sum[OUT_C];
static __device__ float g_sumsq[OUT_C];
static __device__ int   g_ctr;
static __device__ int   g_ctr2;
static __device__ int   g_ctrS;
// CSR
static __device__ int   g_cnt[NMAX];
static __device__ int   g_base[NMAX];     // intra-block exclusive prefix (scan1)
static __device__ int   g_rank[EMAX];     // per-edge rank within its target node
static __device__ int   g_bsum[(NMAX + SCANB - 1) / SCANB];
static __device__ int   g_boff[(NMAX + SCANB - 1) / SCANB];
static __device__ u64   g_pack[EMAX];     // (eid << 32) | src

// ---------------- CSR: histogram + rank capture --------------------------------
__global__ void k_hist(const int* __restrict__ ei, int e_, int n) {
    int i = blockIdx.x * blockDim.x + threadIdx.x;
    if (i >= e_) return;
    int c = ei[e_ + i];
    if ((unsigned)c < (unsigned)n)
        g_rank[i] = atomicAdd(&g_cnt[c], 1);
}

// ---------------- CSR: block scan + fused last-block scan of block sums --------
__global__ void k_scan1(int n, int nb) {
    __shared__ int s[SCANB];
    __shared__ bool isLast;
    int t = threadIdx.x;
    int i = blockIdx.x * SCANB + t;
    int v = (i < n) ? g_cnt[i] : 0;
    s[t] = v;
    __syncthreads();
#pragma unroll
    for (int off = 1; off < SCANB; off <<= 1) {
        int x = (t >= off) ? s[t - off] : 0;
        __syncthreads();
        s[t] += x;
        __syncthreads();
    }
    if (i < n) g_base[i] = s[t] - v;                 // exclusive within block
    if (t == SCANB - 1) {
        g_bsum[blockIdx.x] = s[t];
        __threadfence();
        int old = atomicAdd(&g_ctrS, 1);
        isLast = (old == nb - 1);
    }
    __syncthreads();
    if (isLast) {
        __threadfence();
        __shared__ int bs[128];
        if (t < 128) bs[t] = (t < nb) ? g_bsum[t] : 0;
        __syncthreads();
        if (t < 128) {
#pragma unroll
            for (int off = 1; off < 128; off <<= 1) {
                int x = (t >= off) ? bs[t - off] : 0;
                __syncthreads();
                bs[t] += x;
                __syncthreads();
            }
        } else {
#pragma unroll
            for (int off = 1; off < 128; off <<= 1) { __syncthreads(); __syncthreads(); }
        }
        if (t < nb) g_boff[t] = bs[t] - g_bsum[t];   // exclusive
        if (t == 0) g_ctrS = 0;                      // restore invariant
    }
}

// ---------------- CSR: fill (no atomics; rank precomputed) ---------------------
__global__ void k_fill(const int* __restrict__ ei, int e_, int n) {
    int i = blockIdx.x * blockDim.x + threadIdx.x;
    if (i >= e_) return;
    int r = ei[i];
    int c = ei[e_ + i];
    if ((unsigned)r >= (unsigned)n || (unsigned)c >= (unsigned)n) return;
    int slot = g_base[c] + g_boff[c >> 10] + g_rank[i];
    g_pack[slot] = ((u64)(unsigned)i << 32) | (unsigned)r;
}

// ---------------- edge MLP, f32x2 over h-pairs, 2 edges/thread -----------------
__global__ void k_edge_mlp(const float* __restrict__ ea,
                           const float* __restrict__ w1, const float* __restrict__ b1,
                           const float* __restrict__ w2, const float* __restrict__ b2,
                           const int* __restrict__ ei, int e_, int n) {
    __shared__ __align__(16) float2 swp[16 * 16];
    __shared__ __align__(8)  float2 sb1p[16];
    __shared__ float sw2[EDGE_HID];
    __shared__ float sb2;
    {
        int t = threadIdx.x;
        if (t < 256) {
            int p = t >> 4, i = t & 15;
            swp[t] = make_float2(w1[(2 * p) * EDGE_DIM + i], w1[(2 * p + 1) * EDGE_DIM + i]);
        }
        if (t < 16) sb1p[t] = make_float2(b1[2 * t], b1[2 * t + 1]);
        if (t < EDGE_HID) sw2[t] = w2[t];
        if (t == 0) sb2 = b2[0];
    }
    __syncthreads();

    int e0 = (blockIdx.x * blockDim.x + threadIdx.x) * 2;
    if (e0 >= e_) return;
    bool two = (e0 + 1) < e_;

    u64 a0p[EDGE_DIM], a1p[EDGE_DIM];
    {
        const float4* p = (const float4*)(ea + (long long)e0 * EDGE_DIM);
#pragma unroll
        for (int q = 0; q < 4; q++) {
            float4 v = p[q];
            a0p[q*4+0] = pk(v.x, v.x); a0p[q*4+1] = pk(v.y, v.y);
            a0p[q*4+2] = pk(v.z, v.z); a0p[q*4+3] = pk(v.w, v.w);
            float4 u = two ? p[q + 4] : make_float4(0.f, 0.f, 0.f, 0.f);
            a1p[q*4+0] = pk(u.x, u.x); a1p[q*4+1] = pk(u.y, u.y);
            a1p[q*4+2] = pk(u.z, u.z); a1p[q*4+3] = pk(u.w, u.w);
        }
    }

    float acc0 = sb2, acc1 = sb2;
#pragma unroll 4
    for (int p = 0; p < 16; ++p) {
        float2 sb = sb1p[p];
        u64 s0 = pk(sb.x, sb.y);
        u64 s1 = s0;
#pragma unroll
        for (int iq = 0; iq < 8; ++iq) {
            ulonglong2 w = *(const ulonglong2*)&swp[p * 16 + iq * 2];
            fma2(s0, a0p[iq*2],   w.x);
            fma2(s0, a0p[iq*2+1], w.y);
            fma2(s1, a1p[iq*2],   w.x);
            fma2(s1, a1p[iq*2+1], w.y);
        }
        float wlo = sw2[2*p], whi = sw2[2*p+1];
        float t0, t1;
        upk(s0, t0, t1);
        acc0 = fmaf(fmaxf(t0, 0.f), wlo, fmaf(fmaxf(t1, 0.f), whi, acc0));
        upk(s1, t0, t1);
        acc1 = fmaf(fmaxf(t0, 0.f), wlo, fmaf(fmaxf(t1, 0.f), whi, acc1));
    }
    float g0 = 1.0f / (1.0f + __expf(-acc0));
    g_ew[e0] = g0;
    int c0 = ei[e_ + e0];
    if ((unsigned)c0 < (unsigned)n) atomicAdd(&g_degacc[c0], g0);
    if (two) {
        float g1 = 1.0f / (1.0f + __expf(-acc1));
        g_ew[e0 + 1] = g1;
        int c1 = ei[e_ + e0 + 1];
        if ((unsigned)c1 < (unsigned)n) atomicAdd(&g_degacc[c1], g1);
    }
}

// ---------------- xt = x @ lin_w.T (pure GEMM, fp32/f32x2) ----------------------
#define GR 128
#define KC 32
#define XROW 132
__global__ void __launch_bounds__(256, 3)
k_xt(const float* __restrict__ x, const float* __restrict__ lw, int n) {
    __shared__ __align__(16) float xs[KC][XROW];
    __shared__ __align__(16) float ws[KC][OUT_C];
    int r0 = blockIdx.x * GR;
    int tx = threadIdx.x & 15;
    int ty = threadIdx.x >> 4;
    u64 accp[4][4] = {};

    for (int k0 = 0; k0 < IN_C; k0 += KC) {
        for (int i = threadIdx.x; i < GR * (KC / 4); i += 256) {
            int r = i >> 3, kq = i & 7;
            float4 v = make_float4(0.f, 0.f, 0.f, 0.f);
            if (r0 + r < n) v = *(const float4*)(x + (long long)(r0 + r) * IN_C + k0 + kq * 4);
            xs[kq*4+0][r] = v.x; xs[kq*4+1][r] = v.y;
            xs[kq*4+2][r] = v.z; xs[kq*4+3][r] = v.w;
        }
        for (int i = threadIdx.x; i < OUT_C * (KC / 4); i += 256) {
            int o = i >> 3, kq = i & 7;
            float4 v = *(const float4*)(lw + (long long)o * IN_C + k0 + kq * 4);
            ws[kq*4+0][o] = v.x; ws[kq*4+1][o] = v.y;
            ws[kq*4+2][o] = v.z; ws[kq*4+3][o] = v.w;
        }
        __syncthreads();
#pragma unroll 8
        for (int k = 0; k < KC; ++k) {
            float4 a0 = *(const float4*)&xs[k][ty * 8];
            float4 a1 = *(const float4*)&xs[k][ty * 8 + 4];
            float4 b  = *(const float4*)&ws[k][tx * 4];
            u64 ap0 = pk(a0.x, a0.y), ap1 = pk(a0.z, a0.w);
            u64 ap2 = pk(a1.x, a1.y), ap3 = pk(a1.z, a1.w);
            u64 b0 = pk(b.x, b.x), b1 = pk(b.y, b.y), b2 = pk(b.z, b.z), b3 = pk(b.w, b.w);
            fma2(accp[0][0], ap0, b0); fma2(accp[0][1], ap0, b1);
            fma2(accp[0][2], ap0, b2); fma2(accp[0][3], ap0, b3);
            fma2(accp[1][0], ap1, b0); fma2(accp[1][1], ap1, b1);
            fma2(accp[1][2], ap1, b2); fma2(accp[1][3], ap1, b3);
            fma2(accp[2][0], ap2, b0); fma2(accp[2][1], ap2, b1);
            fma2(accp[2][2], ap2, b2); fma2(accp[2][3], ap2, b3);
            fma2(accp[3][0], ap3, b0); fma2(accp[3][1], ap3, b1);
            fma2(accp[3][2], ap3, b2); fma2(accp[3][3], ap3, b3);
        }
        __syncthreads();
    }
#pragma unroll
    for (int rp = 0; rp < 4; ++rp) {
        float lo[4], hi[4];
#pragma unroll
        for (int j = 0; j < 4; ++j) upk(accp[rp][j], lo[j], hi[j]);
        int rA = r0 + ty * 8 + rp * 2;
        int rB = rA + 1;
        if (rA < n)
            *(float4*)&g_xt[(long long)rA * OUT_C + tx * 4] = make_float4(lo[0], lo[1], lo[2], lo[3]);
        if (rB < n)
            *(float4*)&g_xt[(long long)rB * OUT_C + tx * 4] = make_float4(hi[0], hi[1], hi[2], hi[3]);
    }
}

// ---------------- gather + self-loop + bias + PReLU (1 warp/node) --------------
__global__ void __launch_bounds__(256)
k_gather(float* __restrict__ out, const float* __restrict__ bias,
         const float* __restrict__ pa, int n) {
    int node = blockIdx.x * 8 + (threadIdx.x >> 5);
    if (node >= n) return;
    int lane = threadIdx.x & 31;
    int c0 = lane * 2;
    int beg = g_base[node] + g_boff[node >> 10];
    int cnt = g_cnt[node];
    float2 acc = make_float2(0.f, 0.f);

    for (int j0 = 0; j0 < cnt; j0 += 32) {
        int m = min(32, cnt - j0);
        int src = 0; float a = 0.f;
        if (lane < m) {
            u64 pkd = g_pack[beg + j0 + lane];
            src = (int)(unsigned)(pkd & 0xffffffffu);
            int eid = (int)(unsigned)(pkd >> 32);
            a = rsqrtf(1.0f + g_degacc[src]) * g_ew[eid];
        }
#pragma unroll 4
        for (int j = 0; j < m; ++j) {
            int   s  = __shfl_sync(0xffffffffu, src, j);
            float aj = __shfl_sync(0xffffffffu, a, j);
            float2 v = *(const float2*)&g_xt[(long long)s * OUT_C + c0];
            acc.x = fmaf(aj, v.x, acc.x);
            acc.y = fmaf(aj, v.y, acc.y);
        }
    }
    float dc = rsqrtf(1.0f + g_degacc[node]);
    float d2 = dc * dc;
    float2 xv = *(const float2*)&g_xt[(long long)node * OUT_C + c0];
    float pr = pa[0];
    float v0 = fmaf(d2, xv.x, acc.x * dc) + bias[c0];
    float v1 = fmaf(d2, xv.y, acc.y * dc) + bias[c0 + 1];
    v0 = (v0 >= 0.f) ? v0 : pr * v0;
    v1 = (v1 >= 0.f) ? v1 : pr * v1;
    *(float2*)&out[(long long)node * OUT_C + c0] = make_float2(v0, v1);
}

// ---------------- GraphNorm (resident) + invariant restoration -----------------
__global__ void __launch_bounds__(NTHR, 2)
k_norm(float* __restrict__ y,
       const float* __restrict__ gw, const float* __restrict__ gb,
       const float* __restrict__ gms, int n, int rowsPerBlk) {
    extern __shared__ float sm[];
    __shared__ float ss[NTHR], sq[NTHR];
    __shared__ bool lastBlk;

    int tid = threadIdx.x;
    int c = tid & 63;
    int rl = tid >> 6;
    int r0 = blockIdx.x * rowsPerBlk;
    int r1 = min(n, r0 + rowsPerBlk);

    // restore invariants for arrays dead after k_gather (parallel, hidden)
    for (int i = r0 + tid; i < r1; i += NTHR) {
        g_degacc[i] = 0.0f;
        g_cnt[i] = 0;
    }

    float s = 0.0f, q = 0.0f;
    for (int r = r0 + rl; r < r1; r += NTHR / 64) {
        float v = y[(long long)r * OUT_C + c];
        sm[(r - r0) * OUT_C + c] = v;
        s += v;
        q = fmaf(v, v, q);
    }
    ss[tid] = s; sq[tid] = q;
    __syncthreads();
    if (tid < 64) {
        s = 0.f; q = 0.f;
#pragma unroll
        for (int i = 0; i < NTHR; i += 64) { s += ss[tid + i]; q += sq[tid + i]; }
        atomicAdd(&g_sum[tid], s);
        atomicAdd(&g_sumsq[tid], q);
    }
    __syncthreads();

    if (tid == 0) {
        __threadfence();
        atomicAdd(&g_ctr, 1);
        while (*((volatile int*)&g_ctr) < gridDim.x) __nanosleep(40);
    }
    __syncthreads();
    __threadfence();

    float invn = 1.0f / (float)n;
    float m  = (*((volatile float*)&g_sum[c]))   * invn;
    float qq = (*((volatile float*)&g_sumsq[c])) * invn;
    float sc = gms[c];
    float var = fmaf(-2.0f * sc * m, m, qq) + sc * sc * m * m;
    float w = gw[c] * rsqrtf(var + 1e-5f);
    float smean = sc * m;
    float bb = gb[c];

    for (int r = r0 + rl; r < r1; r += NTHR / 64) {
        long long idx = (long long)r * OUT_C + c;
        y[idx] = fmaf(sm[(r - r0) * OUT_C + c] - smean, w, bb);
    }

    __syncthreads();
    if (tid == 0) {
        __threadfence();
        int old = atomicAdd(&g_ctr2, 1);
        lastBlk = (old == (int)gridDim.x - 1);
    }
    __syncthreads();
    if (lastBlk && tid < 64) {
        g_sum[tid] = 0.0f;
        g_sumsq[tid] = 0.0f;
        if (tid == 0) { g_ctr = 0; g_ctr2 = 0; }
    }
}

// ---------------- launch ---------------------------------------------------------
extern "C" void kernel_launch(void* const* d_in, const int* in_sizes, int n_in,
                              void* d_out, int out_size) {
    const float* x    = (const float*)d_in[0];
    const int*   ei   = (const int*)d_in[1];
    const float* ea   = (const float*)d_in[2];
    const float* lw   = (const float*)d_in[3];
    const float* bias = (const float*)d_in[4];
    const float* w1   = (const float*)d_in[5];
    const float* b1   = (const float*)d_in[6];
    const float* w2   = (const float*)d_in[7];
    const float* b2   = (const float*)d_in[8];
    const float* pa   = (const float*)d_in[9];
    const float* gw   = (const float*)d_in[10];
    const float* gb   = (const float*)d_in[11];
    const float* gms  = (const float*)d_in[12];
    float* out = (float*)d_out;

    int n = in_sizes[0] / IN_C;
    int e = in_sizes[1] / 2;
    int rowsPerBlk = (n + NBLK - 1) / NBLK;
    size_t smBytes = (size_t)rowsPerBlk * OUT_C * sizeof(float);
    int nb = (n + SCANB - 1) / SCANB;

    static cudaStream_t s1 = nullptr, s2 = nullptr;
    static cudaEvent_t evFork = nullptr, evJ1 = nullptr, evJ2 = nullptr;
    if (s1 == nullptr) {
        cudaStreamCreateWithFlags(&s1, cudaStreamNonBlocking);
        cudaStreamCreateWithFlags(&s2, cudaStreamNonBlocking);
        cudaEventCreateWithFlags(&evFork, cudaEventDisableTiming);
        cudaEventCreateWithFlags(&evJ1, cudaEventDisableTiming);
        cudaEventCreateWithFlags(&evJ2, cudaEventDisableTiming);
        cudaFuncSetAttribute(k_norm, cudaFuncAttributeMaxDynamicSharedMemorySize, 96 * 1024);
    }

    cudaEventRecord(evFork, 0);
    cudaStreamWaitEvent(s1, evFork, 0);
    cudaStreamWaitEvent(s2, evFork, 0);

    // stream1: GEMM
    k_xt<<<(n + GR - 1) / GR, 256, 0, s1>>>(x, lw, n);
    cudaEventRecord(evJ1, s1);

    // stream2: CSR build
    k_hist<<<(e + 255) / 256, 256, 0, s2>>>(ei, e, n);
    k_scan1<<<nb, SCANB, 0, s2>>>(n, nb);
    k_fill<<<(e + 255) / 256, 256, 0, s2>>>(ei, e, n);
    cudaEventRecord(evJ2, s2);

    // main stream: edge gate MLP
    int th_mlp = (e + 1) / 2;
    k_edge_mlp<<<(th_mlp + 255) / 256, 256>>>(ea, w1, b1, w2, b2, ei, e, n);

    cudaStreamWaitEvent(0, evJ1, 0);
    cudaStreamWaitEvent(0, evJ2, 0);

    k_gather<<<(n + 7) / 8, 256>>>(out, bias, pa, n);
    k_norm<<<NBLK, NTHR, smBytes>>>(out, gw, gb, gms, n, rowsPerBlk);
}

// round 15
// speedup vs baseline: 1.0849x; 1.0235x over previous
#include <cuda_runtime.h>

#define IN_C    128
#define OUT_C   64
#define EDGE_DIM 16
#define EDGE_HID 32
#define NMAX    100000
#define EMAX    1600000
#define NBLK    296
#define NTHR    512
#define SCANB   1024

typedef unsigned long long u64;

__device__ __forceinline__ u64 pk(float lo, float hi) {
    u64 r; asm("mov.b64 %0, {%1,%2};" : "=l"(r) : "f"(lo), "f"(hi)); return r;
}
__device__ __forceinline__ void upk(u64 v, float& lo, float& hi) {
    asm("mov.b64 {%0,%1}, %2;" : "=f"(lo), "=f"(hi) : "l"(v));
}
__device__ __forceinline__ void fma2(u64& d, u64 a, u64 b) {
    asm("fma.rn.f32x2 %0, %1, %2, %0;" : "+l"(d) : "l"(a), "l"(b));
}

// ---------------- scratch ------------------------------------------------------
// INVARIANT at entry of every kernel_launch (module-load zeros on first call;
// restored by k_norm / k_scan1 every call):
//   g_degacc==0, g_cnt==0, g_sum==0, g_sumsq==0, g_ctr==0, g_ctr2==0, g_ctrS==0
static __device__ float g_ew[EMAX];
static __device__ float g_degacc[NMAX];   // weighted in-degree EXCLUDING self loop
static __device__ float g_xt[(long long)NMAX * OUT_C];
static __device__ float g_sum[OUT_C];
static __device__ float g_sumsq[OUT_C];
static __device__ int   g_ctr;
static __device__ int   g_ctr2;
static __device__ int   g_ctrS;
// CSR
static __device__ int   g_cnt[NMAX];
static __device__ int   g_base[NMAX];     // intra-block exclusive prefix (scan1)
static __device__ int   g_rank[EMAX];     // per-edge rank within its target node
static __device__ int   g_bsum[(NMAX + SCANB - 1) / SCANB];
static __device__ int   g_boff[(NMAX + SCANB - 1) / SCANB];
static __device__ u64   g_pack[EMAX];     // (eid << 32) | src

// ---------------- edge MLP + degree + histogram/rank (fused), 2 edges/thread ---
__global__ void k_edge_mlp(const float* __restrict__ ea,
                           const float* __restrict__ w1, const float* __restrict__ b1,
                           const float* __restrict__ w2, const float* __restrict__ b2,
                           const int* __restrict__ ei, int e_, int n) {
    __shared__ __align__(16) float2 swp[16 * 16];
    __shared__ __align__(8)  float2 sb1p[16];
    __shared__ float sw2[EDGE_HID];
    __shared__ float sb2;
    {
        int t = threadIdx.x;
        if (t < 256) {
            int p = t >> 4, i = t & 15;
            swp[t] = make_float2(w1[(2 * p) * EDGE_DIM + i], w1[(2 * p + 1) * EDGE_DIM + i]);
        }
        if (t < 16) sb1p[t] = make_float2(b1[2 * t], b1[2 * t + 1]);
        if (t < EDGE_HID) sw2[t] = w2[t];
        if (t == 0) sb2 = b2[0];
    }
    __syncthreads();

    int e0 = (blockIdx.x * blockDim.x + threadIdx.x) * 2;
    if (e0 >= e_) return;
    bool two = (e0 + 1) < e_;

    u64 a0p[EDGE_DIM], a1p[EDGE_DIM];
    {
        const float4* p = (const float4*)(ea + (long long)e0 * EDGE_DIM);
#pragma unroll
        for (int q = 0; q < 4; q++) {
            float4 v = p[q];
            a0p[q*4+0] = pk(v.x, v.x); a0p[q*4+1] = pk(v.y, v.y);
            a0p[q*4+2] = pk(v.z, v.z); a0p[q*4+3] = pk(v.w, v.w);
            float4 u = two ? p[q + 4] : make_float4(0.f, 0.f, 0.f, 0.f);
            a1p[q*4+0] = pk(u.x, u.x); a1p[q*4+1] = pk(u.y, u.y);
            a1p[q*4+2] = pk(u.z, u.z); a1p[q*4+3] = pk(u.w, u.w);
        }
    }

    float acc0 = sb2, acc1 = sb2;
#pragma unroll 4
    for (int p = 0; p < 16; ++p) {
        float2 sb = sb1p[p];
        u64 s0 = pk(sb.x, sb.y);
        u64 s1 = s0;
#pragma unroll
        for (int iq = 0; iq < 8; ++iq) {
            ulonglong2 w = *(const ulonglong2*)&swp[p * 16 + iq * 2];
            fma2(s0, a0p[iq*2],   w.x);
            fma2(s0, a0p[iq*2+1], w.y);
            fma2(s1, a1p[iq*2],   w.x);
            fma2(s1, a1p[iq*2+1], w.y);
        }
        float wlo = sw2[2*p], whi = sw2[2*p+1];
        float t0, t1;
        upk(s0, t0, t1);
        acc0 = fmaf(fmaxf(t0, 0.f), wlo, fmaf(fmaxf(t1, 0.f), whi, acc0));
        upk(s1, t0, t1);
        acc1 = fmaf(fmaxf(t0, 0.f), wlo, fmaf(fmaxf(t1, 0.f), whi, acc1));
    }
    float g0 = 1.0f / (1.0f + __expf(-acc0));
    g_ew[e0] = g0;
    int c0 = ei[e_ + e0];
    if ((unsigned)c0 < (unsigned)n) {
        atomicAdd(&g_degacc[c0], g0);
        g_rank[e0] = atomicAdd(&g_cnt[c0], 1);
    }
    if (two) {
        float g1 = 1.0f / (1.0f + __expf(-acc1));
        g_ew[e0 + 1] = g1;
        int c1 = ei[e_ + e0 + 1];
        if ((unsigned)c1 < (unsigned)n) {
            atomicAdd(&g_degacc[c1], g1);
            g_rank[e0 + 1] = atomicAdd(&g_cnt[c1], 1);
        }
    }
}

// ---------------- CSR: block scan + fused last-block scan of block sums --------
__global__ void k_scan1(int n, int nb) {
    __shared__ int s[SCANB];
    __shared__ bool isLast;
    int t = threadIdx.x;
    int i = blockIdx.x * SCANB + t;
    int v = (i < n) ? g_cnt[i] : 0;
    s[t] = v;
    __syncthreads();
#pragma unroll
    for (int off = 1; off < SCANB; off <<= 1) {
        int x = (t >= off) ? s[t - off] : 0;
        __syncthreads();
        s[t] += x;
        __syncthreads();
    }
    if (i < n) g_base[i] = s[t] - v;                 // exclusive within block
    if (t == SCANB - 1) {
        g_bsum[blockIdx.x] = s[t];
        __threadfence();
        int old = atomicAdd(&g_ctrS, 1);
        isLast = (old == nb - 1);
    }
    __syncthreads();
    if (isLast) {
        __threadfence();
        __shared__ int bs[128];
        if (t < 128) bs[t] = (t < nb) ? g_bsum[t] : 0;
        __syncthreads();
        if (t < 128) {
#pragma unroll
            for (int off = 1; off < 128; off <<= 1) {
                int x = (t >= off) ? bs[t - off] : 0;
                __syncthreads();
                bs[t] += x;
                __syncthreads();
            }
        } else {
#pragma unroll
            for (int off = 1; off < 128; off <<= 1) { __syncthreads(); __syncthreads(); }
        }
        if (t < nb) g_boff[t] = bs[t] - g_bsum[t];   // exclusive
        if (t == 0) g_ctrS = 0;                      // restore invariant
    }
}

// ---------------- CSR: fill (no atomics; rank precomputed) ---------------------
__global__ void k_fill(const int* __restrict__ ei, int e_, int n) {
    int i = blockIdx.x * blockDim.x + threadIdx.x;
    if (i >= e_) return;
    int r = ei[i];
    int c = ei[e_ + i];
    if ((unsigned)r >= (unsigned)n || (unsigned)c >= (unsigned)n) return;
    int slot = g_base[c] + g_boff[c >> 10] + g_rank[i];
    g_pack[slot] = ((u64)(unsigned)i << 32) | (unsigned)r;
}

// ---------------- xt = x @ lin_w.T (pure GEMM, fp32/f32x2) ----------------------
#define GR 128
#define KC 32
#define XROW 132
__global__ void __launch_bounds__(256, 3)
k_xt(const float* __restrict__ x, const float* __restrict__ lw, int n) {
    __shared__ __align__(16) float xs[KC][XROW];
    __shared__ __align__(16) float ws[KC][OUT_C];
    int r0 = blockIdx.x * GR;
    int tx = threadIdx.x & 15;
    int ty = threadIdx.x >> 4;
    u64 accp[4][4] = {};

    for (int k0 = 0; k0 < IN_C; k0 += KC) {
        for (int i = threadIdx.x; i < GR * (KC / 4); i += 256) {
            int r = i >> 3, kq = i & 7;
            float4 v = make_float4(0.f, 0.f, 0.f, 0.f);
            if (r0 + r < n) v = *(const float4*)(x + (long long)(r0 + r) * IN_C + k0 + kq * 4);
            xs[kq*4+0][r] = v.x; xs[kq*4+1][r] = v.y;
            xs[kq*4+2][r] = v.z; xs[kq*4+3][r] = v.w;
        }
        for (int i = threadIdx.x; i < OUT_C * (KC / 4); i += 256) {
            int o = i >> 3, kq = i & 7;
            float4 v = *(const float4*)(lw + (long long)o * IN_C + k0 + kq * 4);
            ws[kq*4+0][o] = v.x; ws[kq*4+1][o] = v.y;
            ws[kq*4+2][o] = v.z; ws[kq*4+3][o] = v.w;
        }
        __syncthreads();
#pragma unroll 8
        for (int k = 0; k < KC; ++k) {
            float4 a0 = *(const float4*)&xs[k][ty * 8];
            float4 a1 = *(const float4*)&xs[k][ty * 8 + 4];
            float4 b  = *(const float4*)&ws[k][tx * 4];
            u64 ap0 = pk(a0.x, a0.y), ap1 = pk(a0.z, a0.w);
            u64 ap2 = pk(a1.x, a1.y), ap3 = pk(a1.z, a1.w);
            u64 b0 = pk(b.x, b.x), b1 = pk(b.y, b.y), b2 = pk(b.z, b.z), b3 = pk(b.w, b.w);
            fma2(accp[0][0], ap0, b0); fma2(accp[0][1], ap0, b1);
            fma2(accp[0][2], ap0, b2); fma2(accp[0][3], ap0, b3);
            fma2(accp[1][0], ap1, b0); fma2(accp[1][1], ap1, b1);
            fma2(accp[1][2], ap1, b2); fma2(accp[1][3], ap1, b3);
            fma2(accp[2][0], ap2, b0); fma2(accp[2][1], ap2, b1);
            fma2(accp[2][2], ap2, b2); fma2(accp[2][3], ap2, b3);
            fma2(accp[3][0], ap3, b0); fma2(accp[3][1], ap3, b1);
            fma2(accp[3][2], ap3, b2); fma2(accp[3][3], ap3, b3);
        }
        __syncthreads();
    }
#pragma unroll
    for (int rp = 0; rp < 4; ++rp) {
        float lo[4], hi[4];
#pragma unroll
        for (int j = 0; j < 4; ++j) upk(accp[rp][j], lo[j], hi[j]);
        int rA = r0 + ty * 8 + rp * 2;
        int rB = rA + 1;
        if (rA < n)
            *(float4*)&g_xt[(long long)rA * OUT_C + tx * 4] = make_float4(lo[0], lo[1], lo[2], lo[3]);
        if (rB < n)
            *(float4*)&g_xt[(long long)rB * OUT_C + tx * 4] = make_float4(hi[0], hi[1], hi[2], hi[3]);
    }
}

// ---------------- gather + self-loop + bias + PReLU (1 warp/node) --------------
__global__ void __launch_bounds__(256)
k_gather(float* __restrict__ out, const float* __restrict__ bias,
         const float* __restrict__ pa, int n) {
    int node = blockIdx.x * 8 + (threadIdx.x >> 5);
    if (node >= n) return;
    int lane = threadIdx.x & 31;
    int c0 = lane * 2;
    int beg = g_base[node] + g_boff[node >> 10];
    int cnt = g_cnt[node];
    float2 acc = make_float2(0.f, 0.f);

    for (int j0 = 0; j0 < cnt; j0 += 32) {
        int m = min(32, cnt - j0);
        int src = 0; float a = 0.f;
        if (lane < m) {
            u64 pkd = g_pack[beg + j0 + lane];
            src = (int)(unsigned)(pkd & 0xffffffffu);
            int eid = (int)(unsigned)(pkd >> 32);
            a = rsqrtf(1.0f + g_degacc[src]) * g_ew[eid];
        }
#pragma unroll 4
        for (int j = 0; j < m; ++j) {
            int   s  = __shfl_sync(0xffffffffu, src, j);
            float aj = __shfl_sync(0xffffffffu, a, j);
            float2 v = *(const float2*)&g_xt[(long long)s * OUT_C + c0];
            acc.x = fmaf(aj, v.x, acc.x);
            acc.y = fmaf(aj, v.y, acc.y);
        }
    }
    float dc = rsqrtf(1.0f + g_degacc[node]);
    float d2 = dc * dc;
    float2 xv = *(const float2*)&g_xt[(long long)node * OUT_C + c0];
    float pr = pa[0];
    float v0 = fmaf(d2, xv.x, acc.x * dc) + bias[c0];
    float v1 = fmaf(d2, xv.y, acc.y * dc) + bias[c0 + 1];
    v0 = (v0 >= 0.f) ? v0 : pr * v0;
    v1 = (v1 >= 0.f) ? v1 : pr * v1;
    *(float2*)&out[(long long)node * OUT_C + c0] = make_float2(v0, v1);
}

// ---------------- GraphNorm (resident) + invariant restoration -----------------
__global__ void __launch_bounds__(NTHR, 2)
k_norm(float* __restrict__ y,
       const float* __restrict__ gw, const float* __restrict__ gb,
       const float* __restrict__ gms, int n, int rowsPerBlk) {
    extern __shared__ float sm[];
    __shared__ float ss[NTHR], sq[NTHR];
    __shared__ bool lastBlk;

    int tid = threadIdx.x;
    int c = tid & 63;
    int rl = tid >> 6;
    int r0 = blockIdx.x * rowsPerBlk;
    int r1 = min(n, r0 + rowsPerBlk);

    // restore invariants for arrays dead after k_gather (parallel, hidden)
    for (int i = r0 + tid; i < r1; i += NTHR) {
        g_degacc[i] = 0.0f;
        g_cnt[i] = 0;
    }

    float s = 0.0f, q = 0.0f;
    for (int r = r0 + rl; r < r1; r += NTHR / 64) {
        float v = y[(long long)r * OUT_C + c];
        sm[(r - r0) * OUT_C + c] = v;
        s += v;
        q = fmaf(v, v, q);
    }
    ss[tid] = s; sq[tid] = q;
    __syncthreads();
    if (tid < 64) {
        s = 0.f; q = 0.f;
#pragma unroll
        for (int i = 0; i < NTHR; i += 64) { s += ss[tid + i]; q += sq[tid + i]; }
        atomicAdd(&g_sum[tid], s);
        atomicAdd(&g_sumsq[tid], q);
    }
    __syncthreads();

    if (tid == 0) {
        __threadfence();
        atomicAdd(&g_ctr, 1);
        while (*((volatile int*)&g_ctr) < gridDim.x) __nanosleep(40);
    }
    __syncthreads();
    __threadfence();

    float invn = 1.0f / (float)n;
    float m  = (*((volatile float*)&g_sum[c]))   * invn;
    float qq = (*((volatile float*)&g_sumsq[c])) * invn;
    float sc = gms[c];
    float var = fmaf(-2.0f * sc * m, m, qq) + sc * sc * m * m;
    float w = gw[c] * rsqrtf(var + 1e-5f);
    float smean = sc * m;
    float bb = gb[c];

    for (int r = r0 + rl; r < r1; r += NTHR / 64) {
        long long idx = (long long)r * OUT_C + c;
        y[idx] = fmaf(sm[(r - r0) * OUT_C + c] - smean, w, bb);
    }

    __syncthreads();
    if (tid == 0) {
        __threadfence();
        int old = atomicAdd(&g_ctr2, 1);
        lastBlk = (old == (int)gridDim.x - 1);
    }
    __syncthreads();
    if (lastBlk && tid < 64) {
        g_sum[tid] = 0.0f;
        g_sumsq[tid] = 0.0f;
        if (tid == 0) { g_ctr = 0; g_ctr2 = 0; }
    }
}

// ---------------- launch ---------------------------------------------------------
extern "C" void kernel_launch(void* const* d_in, const int* in_sizes, int n_in,
                              void* d_out, int out_size) {
    const float* x    = (const float*)d_in[0];
    const int*   ei   = (const int*)d_in[1];
    const float* ea   = (const float*)d_in[2];
    const float* lw   = (const float*)d_in[3];
    const float* bias = (const float*)d_in[4];
    const float* w1   = (const float*)d_in[5];
    const float* b1   = (const float*)d_in[6];
    const float* w2   = (const float*)d_in[7];
    const float* b2   = (const float*)d_in[8];
    const float* pa   = (const float*)d_in[9];
    const float* gw   = (const float*)d_in[10];
    const float* gb   = (const float*)d_in[11];
    const float* gms  = (const float*)d_in[12];
    float* out = (float*)d_out;

    int n = in_sizes[0] / IN_C;
    int e = in_sizes[1] / 2;
    int rowsPerBlk = (n + NBLK - 1) / NBLK;
    size_t smBytes = (size_t)rowsPerBlk * OUT_C * sizeof(float);
    int nb = (n + SCANB - 1) / SCANB;

    static cudaStream_t s1 = nullptr;
    static cudaEvent_t evFork = nullptr, evJ1 = nullptr;
    if (s1 == nullptr) {
        cudaStreamCreateWithFlags(&s1, cudaStreamNonBlocking);
        cudaEventCreateWithFlags(&evFork, cudaEventDisableTiming);
        cudaEventCreateWithFlags(&evJ1, cudaEventDisableTiming);
        cudaFuncSetAttribute(k_norm, cudaFuncAttributeMaxDynamicSharedMemorySize, 96 * 1024);
    }

    cudaEventRecord(evFork, 0);
    cudaStreamWaitEvent(s1, evFork, 0);

    // stream1: GEMM (fully independent)
    k_xt<<<(n + GR - 1) / GR, 256, 0, s1>>>(x, lw, n);
    cudaEventRecord(evJ1, s1);

    // main stream: fused edge MLP (+hist/rank) -> scan -> fill
    int th_mlp = (e + 1) / 2;
    k_edge_mlp<<<(th_mlp + 255) / 256, 256>>>(ea, w1, b1, w2, b2, ei, e, n);
    k_scan1<<<nb, SCANB>>>(n, nb);
    k_fill<<<(e + 255) / 256, 256>>>(ei, e, n);

    cudaStreamWaitEvent(0, evJ1, 0);

    k_gather<<<(n + 7) / 8, 256>>>(out, bias, pa, n);
    k_norm<<<NBLK, NTHR, smBytes>>>(out, gw, gb, gms, n, rowsPerBlk);
}

// round 16
// speedup vs baseline: 1.1287x; 1.0404x over previous
#include <cuda_runtime.h>

#define IN_C    128
#define OUT_C   64
#define EDGE_DIM 16
#define EDGE_HID 32
#define NMAX    100000
#define EMAX    1600000
#define NBLK    296
#define NTHR    512
#define SCANB   1024

typedef unsigned long long u64;

__device__ __forceinline__ u64 pk(float lo, float hi) {
    u64 r; asm("mov.b64 %0, {%1,%2};" : "=l"(r) : "f"(lo), "f"(hi)); return r;
}
__device__ __forceinline__ void upk(u64 v, float& lo, float& hi) {
    asm("mov.b64 {%0,%1}, %2;" : "=f"(lo), "=f"(hi) : "l"(v));
}
__device__ __forceinline__ void fma2(u64& d, u64 a, u64 b) {
    asm("fma.rn.f32x2 %0, %1, %2, %0;" : "+l"(d) : "l"(a), "l"(b));
}

// ---------------- scratch ------------------------------------------------------
// INVARIANT at entry of every kernel_launch (module-load zeros on first call;
// restored by k_norm / k_scan1 every call):
//   g_degacc==0, g_cnt==0, g_sum==0, g_sumsq==0, g_ctr==0, g_ctr2==0, g_ctrS==0
static __device__ float g_ew[EMAX];
static __device__ float g_degacc[NMAX];   // weighted in-degree EXCLUDING self loop
static __device__ float g_dinv[NMAX];     // rsqrt(1+degacc) — fully rewritten by scan1
static __device__ float g_xt[(long long)NMAX * OUT_C];
static __device__ float g_sum[OUT_C];
static __device__ float g_sumsq[OUT_C];
static __device__ int   g_ctr;
static __device__ int   g_ctr2;
static __device__ int   g_ctrS;
// CSR
static __device__ int   g_cnt[NMAX];
static __device__ int   g_base[NMAX];     // intra-block exclusive prefix (scan1)
static __device__ int   g_rank[EMAX];     // per-edge rank within its target node
static __device__ int   g_bsum[(NMAX + SCANB - 1) / SCANB];
static __device__ int   g_boff[(NMAX + SCANB - 1) / SCANB];
static __device__ u64   g_pack[EMAX];     // (f32bits(a) << 32) | src

// ---------------- edge MLP + degree + histogram/rank (fused), 2 edges/thread ---
__global__ void k_edge_mlp(const float* __restrict__ ea,
                           const float* __restrict__ w1, const float* __restrict__ b1,
                           const float* __restrict__ w2, const float* __restrict__ b2,
                           const int* __restrict__ ei, int e_, int n) {
    __shared__ __align__(16) float2 swp[16 * 16];
    __shared__ __align__(8)  float2 sb1p[16];
    __shared__ float sw2[EDGE_HID];
    __shared__ float sb2;
    {
        int t = threadIdx.x;
        if (t < 256) {
            int p = t >> 4, i = t & 15;
            swp[t] = make_float2(w1[(2 * p) * EDGE_DIM + i], w1[(2 * p + 1) * EDGE_DIM + i]);
        }
        if (t < 16) sb1p[t] = make_float2(b1[2 * t], b1[2 * t + 1]);
        if (t < EDGE_HID) sw2[t] = w2[t];
        if (t == 0) sb2 = b2[0];
    }
    __syncthreads();

    int e0 = (blockIdx.x * blockDim.x + threadIdx.x) * 2;
    if (e0 >= e_) return;
    bool two = (e0 + 1) < e_;

    u64 a0p[EDGE_DIM], a1p[EDGE_DIM];
    {
        const float4* p = (const float4*)(ea + (long long)e0 * EDGE_DIM);
#pragma unroll
        for (int q = 0; q < 4; q++) {
            float4 v = p[q];
            a0p[q*4+0] = pk(v.x, v.x); a0p[q*4+1] = pk(v.y, v.y);
            a0p[q*4+2] = pk(v.z, v.z); a0p[q*4+3] = pk(v.w, v.w);
            float4 u = two ? p[q + 4] : make_float4(0.f, 0.f, 0.f, 0.f);
            a1p[q*4+0] = pk(u.x, u.x); a1p[q*4+1] = pk(u.y, u.y);
            a1p[q*4+2] = pk(u.z, u.z); a1p[q*4+3] = pk(u.w, u.w);
        }
    }

    float acc0 = sb2, acc1 = sb2;
#pragma unroll 4
    for (int p = 0; p < 16; ++p) {
        float2 sb = sb1p[p];
        u64 s0 = pk(sb.x, sb.y);
        u64 s1 = s0;
#pragma unroll
        for (int iq = 0; iq < 8; ++iq) {
            ulonglong2 w = *(const ulonglong2*)&swp[p * 16 + iq * 2];
            fma2(s0, a0p[iq*2],   w.x);
            fma2(s0, a0p[iq*2+1], w.y);
            fma2(s1, a1p[iq*2],   w.x);
            fma2(s1, a1p[iq*2+1], w.y);
        }
        float wlo = sw2[2*p], whi = sw2[2*p+1];
        float t0, t1;
        upk(s0, t0, t1);
        acc0 = fmaf(fmaxf(t0, 0.f), wlo, fmaf(fmaxf(t1, 0.f), whi, acc0));
        upk(s1, t0, t1);
        acc1 = fmaf(fmaxf(t0, 0.f), wlo, fmaf(fmaxf(t1, 0.f), whi, acc1));
    }
    float g0 = 1.0f / (1.0f + __expf(-acc0));
    g_ew[e0] = g0;
    int c0 = ei[e_ + e0];
    if ((unsigned)c0 < (unsigned)n) {
        atomicAdd(&g_degacc[c0], g0);
        g_rank[e0] = atomicAdd(&g_cnt[c0], 1);
    }
    if (two) {
        float g1 = 1.0f / (1.0f + __expf(-acc1));
        g_ew[e0 + 1] = g1;
        int c1 = ei[e_ + e0 + 1];
        if ((unsigned)c1 < (unsigned)n) {
            atomicAdd(&g_degacc[c1], g1);
            g_rank[e0 + 1] = atomicAdd(&g_cnt[c1], 1);
        }
    }
}

// ---------------- CSR: block scan + block-sum scan + dinv ----------------------
__global__ void k_scan1(int n, int nb) {
    __shared__ int s[SCANB];
    __shared__ bool isLast;
    int t = threadIdx.x;
    int i = blockIdx.x * SCANB + t;
    int v = (i < n) ? g_cnt[i] : 0;
    if (i < n) g_dinv[i] = rsqrtf(1.0f + g_degacc[i]);   // dinv for fill/gather
    s[t] = v;
    __syncthreads();
#pragma unroll
    for (int off = 1; off < SCANB; off <<= 1) {
        int x = (t >= off) ? s[t - off] : 0;
        __syncthreads();
        s[t] += x;
        __syncthreads();
    }
    if (i < n) g_base[i] = s[t] - v;                 // exclusive within block
    if (t == SCANB - 1) {
        g_bsum[blockIdx.x] = s[t];
        __threadfence();
        int old = atomicAdd(&g_ctrS, 1);
        isLast = (old == nb - 1);
    }
    __syncthreads();
    if (isLast) {
        __threadfence();
        __shared__ int bs[128];
        if (t < 128) bs[t] = (t < nb) ? g_bsum[t] : 0;
        __syncthreads();
        if (t < 128) {
#pragma unroll
            for (int off = 1; off < 128; off <<= 1) {
                int x = (t >= off) ? bs[t - off] : 0;
                __syncthreads();
                bs[t] += x;
                __syncthreads();
            }
        } else {
#pragma unroll
            for (int off = 1; off < 128; off <<= 1) { __syncthreads(); __syncthreads(); }
        }
        if (t < nb) g_boff[t] = bs[t] - g_bsum[t];   // exclusive
        if (t == 0) g_ctrS = 0;                      // restore invariant
    }
}

// ---------------- CSR: fill (no atomics; payload carries edge weight) ----------
__global__ void k_fill(const int* __restrict__ ei, int e_, int n) {
    int i = blockIdx.x * blockDim.x + threadIdx.x;
    if (i >= e_) return;
    int r = ei[i];
    int c = ei[e_ + i];
    if ((unsigned)r >= (unsigned)n || (unsigned)c >= (unsigned)n) return;
    int slot = g_base[c] + g_boff[c >> 10] + g_rank[i];
    float a = g_dinv[r] * g_ew[i];
    g_pack[slot] = ((u64)__float_as_uint(a) << 32) | (unsigned)r;
}

// ---------------- xt = x @ lin_w.T (pure GEMM, fp32/f32x2) ----------------------
#define GR 128
#define KC 32
#define XROW 132
__global__ void __launch_bounds__(256, 3)
k_xt(const float* __restrict__ x, const float* __restrict__ lw, int n) {
    __shared__ __align__(16) float xs[KC][XROW];
    __shared__ __align__(16) float ws[KC][OUT_C];
    int r0 = blockIdx.x * GR;
    int tx = threadIdx.x & 15;
    int ty = threadIdx.x >> 4;
    u64 accp[4][4] = {};

    for (int k0 = 0; k0 < IN_C; k0 += KC) {
        for (int i = threadIdx.x; i < GR * (KC / 4); i += 256) {
            int r = i >> 3, kq = i & 7;
            float4 v = make_float4(0.f, 0.f, 0.f, 0.f);
            if (r0 + r < n) v = *(const float4*)(x + (long long)(r0 + r) * IN_C + k0 + kq * 4);
            xs[kq*4+0][r] = v.x; xs[kq*4+1][r] = v.y;
            xs[kq*4+2][r] = v.z; xs[kq*4+3][r] = v.w;
        }
        for (int i = threadIdx.x; i < OUT_C * (KC / 4); i += 256) {
            int o = i >> 3, kq = i & 7;
            float4 v = *(const float4*)(lw + (long long)o * IN_C + k0 + kq * 4);
            ws[kq*4+0][o] = v.x; ws[kq*4+1][o] = v.y;
            ws[kq*4+2][o] = v.z; ws[kq*4+3][o] = v.w;
        }
        __syncthreads();
#pragma unroll 8
        for (int k = 0; k < KC; ++k) {
            float4 a0 = *(const float4*)&xs[k][ty * 8];
            float4 a1 = *(const float4*)&xs[k][ty * 8 + 4];
            float4 b  = *(const float4*)&ws[k][tx * 4];
            u64 ap0 = pk(a0.x, a0.y), ap1 = pk(a0.z, a0.w);
            u64 ap2 = pk(a1.x, a1.y), ap3 = pk(a1.z, a1.w);
            u64 b0 = pk(b.x, b.x), b1 = pk(b.y, b.y), b2 = pk(b.z, b.z), b3 = pk(b.w, b.w);
            fma2(accp[0][0], ap0, b0); fma2(accp[0][1], ap0, b1);
            fma2(accp[0][2], ap0, b2); fma2(accp[0][3], ap0, b3);
            fma2(accp[1][0], ap1, b0); fma2(accp[1][1], ap1, b1);
            fma2(accp[1][2], ap1, b2); fma2(accp[1][3], ap1, b3);
            fma2(accp[2][0], ap2, b0); fma2(accp[2][1], ap2, b1);
            fma2(accp[2][2], ap2, b2); fma2(accp[2][3], ap2, b3);
            fma2(accp[3][0], ap3, b0); fma2(accp[3][1], ap3, b1);
            fma2(accp[3][2], ap3, b2); fma2(accp[3][3], ap3, b3);
        }
        __syncthreads();
    }
#pragma unroll
    for (int rp = 0; rp < 4; ++rp) {
        float lo[4], hi[4];
#pragma unroll
        for (int j = 0; j < 4; ++j) upk(accp[rp][j], lo[j], hi[j]);
        int rA = r0 + ty * 8 + rp * 2;
        int rB = rA + 1;
        if (rA < n)
            *(float4*)&g_xt[(long long)rA * OUT_C + tx * 4] = make_float4(lo[0], lo[1], lo[2], lo[3]);
        if (rB < n)
            *(float4*)&g_xt[(long long)rB * OUT_C + tx * 4] = make_float4(hi[0], hi[1], hi[2], hi[3]);
    }
}

// ---------------- gather + self-loop + bias + PReLU (1 warp/node) --------------
__global__ void __launch_bounds__(256)
k_gather(float* __restrict__ out, const float* __restrict__ bias,
         const float* __restrict__ pa, int n) {
    int node = blockIdx.x * 8 + (threadIdx.x >> 5);
    if (node >= n) return;
    int lane = threadIdx.x & 31;
    int c0 = lane * 2;
    int beg = g_base[node] + g_boff[node >> 10];
    int cnt = g_cnt[node];
    float2 acc = make_float2(0.f, 0.f);

    for (int j0 = 0; j0 < cnt; j0 += 32) {
        int m = min(32, cnt - j0);
        int src = 0; float a = 0.f;
        if (lane < m) {
            u64 pkd = g_pack[beg + j0 + lane];
            src = (int)(unsigned)(pkd & 0xffffffffu);
            a = __uint_as_float((unsigned)(pkd >> 32));
        }
#pragma unroll 4
        for (int j = 0; j < m; ++j) {
            int   s  = __shfl_sync(0xffffffffu, src, j);
            float aj = __shfl_sync(0xffffffffu, a, j);
            float2 v = *(const float2*)&g_xt[(long long)s * OUT_C + c0];
            acc.x = fmaf(aj, v.x, acc.x);
            acc.y = fmaf(aj, v.y, acc.y);
        }
    }
    float dc = g_dinv[node];
    float d2 = dc * dc;
    float2 xv = *(const float2*)&g_xt[(long long)node * OUT_C + c0];
    float pr = pa[0];
    float v0 = fmaf(d2, xv.x, acc.x * dc) + bias[c0];
    float v1 = fmaf(d2, xv.y, acc.y * dc) + bias[c0 + 1];
    v0 = (v0 >= 0.f) ? v0 : pr * v0;
    v1 = (v1 >= 0.f) ? v1 : pr * v1;
    *(float2*)&out[(long long)node * OUT_C + c0] = make_float2(v0, v1);
}

// ---------------- GraphNorm (resident) + invariant restoration -----------------
__global__ void __launch_bounds__(NTHR, 2)
k_norm(float* __restrict__ y,
       const float* __restrict__ gw, const float* __restrict__ gb,
       const float* __restrict__ gms, int n, int rowsPerBlk) {
    extern __shared__ float sm[];
    __shared__ float ss[NTHR], sq[NTHR];
    __shared__ bool lastBlk;

    int tid = threadIdx.x;
    int c = tid & 63;
    int rl = tid >> 6;
    int r0 = blockIdx.x * rowsPerBlk;
    int r1 = min(n, r0 + rowsPerBlk);

    // restore invariants for arrays dead after k_gather (parallel, hidden)
    for (int i = r0 + tid; i < r1; i += NTHR) {
        g_degacc[i] = 0.0f;
        g_cnt[i] = 0;
    }

    float s = 0.0f, q = 0.0f;
    for (int r = r0 + rl; r < r1; r += NTHR / 64) {
        float v = y[(long long)r * OUT_C + c];
        sm[(r - r0) * OUT_C + c] = v;
        s += v;
        q = fmaf(v, v, q);
    }
    ss[tid] = s; sq[tid] = q;
    __syncthreads();
    if (tid < 64) {
        s = 0.f; q = 0.f;
#pragma unroll
        for (int i = 0; i < NTHR; i += 64) { s += ss[tid + i]; q += sq[tid + i]; }
        atomicAdd(&g_sum[tid], s);
        atomicAdd(&g_sumsq[tid], q);
    }
    __syncthreads();

    if (tid == 0) {
        __threadfence();
        atomicAdd(&g_ctr, 1);
        while (*((volatile int*)&g_ctr) < gridDim.x) __nanosleep(40);
    }
    __syncthreads();
    __threadfence();

    float invn = 1.0f / (float)n;
    float m  = (*((volatile float*)&g_sum[c]))   * invn;
    float qq = (*((volatile float*)&g_sumsq[c])) * invn;
    float sc = gms[c];
    float var = fmaf(-2.0f * sc * m, m, qq) + sc * sc * m * m;
    float w = gw[c] * rsqrtf(var + 1e-5f);
    float smean = sc * m;
    float bb = gb[c];

    for (int r = r0 + rl; r < r1; r += NTHR / 64) {
        long long idx = (long long)r * OUT_C + c;
        y[idx] = fmaf(sm[(r - r0) * OUT_C + c] - smean, w, bb);
    }

    __syncthreads();
    if (tid == 0) {
        __threadfence();
        int old = atomicAdd(&g_ctr2, 1);
        lastBlk = (old == (int)gridDim.x - 1);
    }
    __syncthreads();
    if (lastBlk && tid < 64) {
        g_sum[tid] = 0.0f;
        g_sumsq[tid] = 0.0f;
        if (tid == 0) { g_ctr = 0; g_ctr2 = 0; }
    }
}

// ---------------- launch ---------------------------------------------------------
extern "C" void kernel_launch(void* const* d_in, const int* in_sizes, int n_in,
                              void* d_out, int out_size) {
    const float* x    = (const float*)d_in[0];
    const int*   ei   = (const int*)d_in[1];
    const float* ea   = (const float*)d_in[2];
    const float* lw   = (const float*)d_in[3];
    const float* bias = (const float*)d_in[4];
    const float* w1   = (const float*)d_in[5];
    const float* b1   = (const float*)d_in[6];
    const float* w2   = (const float*)d_in[7];
    const float* b2   = (const float*)d_in[8];
    const float* pa   = (const float*)d_in[9];
    const float* gw   = (const float*)d_in[10];
    const float* gb   = (const float*)d_in[11];
    const float* gms  = (const float*)d_in[12];
    float* out = (float*)d_out;

    int n = in_sizes[0] / IN_C;
    int e = in_sizes[1] / 2;
    int rowsPerBlk = (n + NBLK - 1) / NBLK;
    size_t smBytes = (size_t)rowsPerBlk * OUT_C * sizeof(float);
    int nb = (n + SCANB - 1) / SCANB;

    static cudaStream_t s1 = nullptr;
    static cudaEvent_t evFork = nullptr, evJ1 = nullptr;
    if (s1 == nullptr) {
        cudaStreamCreateWithFlags(&s1, cudaStreamNonBlocking);
        cudaEventCreateWithFlags(&evFork, cudaEventDisableTiming);
        cudaEventCreateWithFlags(&evJ1, cudaEventDisableTiming);
        cudaFuncSetAttribute(k_norm, cudaFuncAttributeMaxDynamicSharedMemorySize, 96 * 1024);
    }

    cudaEventRecord(evFork, 0);
    cudaStreamWaitEvent(s1, evFork, 0);

    // stream1: GEMM (fully independent)
    k_xt<<<(n + GR - 1) / GR, 256, 0, s1>>>(x, lw, n);
    cudaEventRecord(evJ1, s1);

    // main stream: fused edge MLP (+hist/rank) -> scan(+dinv) -> fill(+weights)
    int th_mlp = (e + 1) / 2;
    k_edge_mlp<<<(th_mlp + 255) / 256, 256>>>(ea, w1, b1, w2, b2, ei, e, n);
    k_scan1<<<nb, SCANB>>>(n, nb);
    k_fill<<<(e + 255) / 256, 256>>>(ei, e, n);

    cudaStreamWaitEvent(0, evJ1, 0);

    k_gather<<<(n + 7) / 8, 256>>>(out, bias, pa, n);
    k_norm<<<NBLK, NTHR, smBytes>>>(out, gw, gb, gms, n, rowsPerBlk);
}